// round 6
// baseline (speedup 1.0000x reference)
#include <cuda_runtime.h>
#include <cuda_bf16.h>

// ChamferLoss via exact uniform-grid nearest neighbor.
// pred[32768,3], target[32768,3] float32, out = mean NN^2 both directions.
//
// Pipeline (all graph-capturable, allocation-free):
//  1. zero counts   2. histogram cells   3-5. hierarchical exclusive scan (CSR)
//  6. scatter points (sorted by cell, carrying original index)
//  7. query: expanding Chebyshev-ring search with exact termination bound
//  8-9. deterministic 2-stage sum.

#define NPTS   32768
#define NALL   65536
#define G      64
#define NC     (G*G*G)       // 262144 cells per set
#define NC2    (2*NC)        // both sets concatenated
#define GLO    (-4.0f)
#define GH     (0.125f)      // 8/64, exact
#define GINV   (8.0f)        // 1/GH, exact
#define FINF   3.4e38f
#define RED1_BLOCKS 64

__device__ uint    g_cnt[NC2];
__device__ uint    g_scanpart[NC2];
__device__ uint    g_bsum[512];
__device__ uint    g_boff[512];
__device__ uint    g_start[NC2 + 1];
__device__ uint    g_cursor[NC2];
__device__ float4  g_pts[NALL];      // sorted by cell; .w = original global idx bits
__device__ float   g_minv[NALL];     // per-ORIGINAL-index min sq distance
__device__ float   g_part[RED1_BLOCKS];

__device__ __forceinline__ int cellof(float v) {
    int c = (int)floorf((v - GLO) * GINV);
    return min(max(c, 0), G - 1);
}

// ---------------- 1. zero counts ----------------
__global__ void __launch_bounds__(256) k_zero() {
    int i = (blockIdx.x * 256 + threadIdx.x) * 4;
    g_cnt[i] = 0; g_cnt[i + 1] = 0; g_cnt[i + 2] = 0; g_cnt[i + 3] = 0;
}

// ---------------- 2. histogram ----------------
__global__ void __launch_bounds__(256) k_hist(const float* __restrict__ pred,
                                              const float* __restrict__ target) {
    int i = blockIdx.x * 256 + threadIdx.x;          // 0..NALL-1
    int s = i >> 15;
    int li = i & (NPTS - 1);
    const float* src = s ? target : pred;
    float x = src[3 * li], y = src[3 * li + 1], z = src[3 * li + 2];
    int c = ((cellof(z) * G + cellof(y)) * G + cellof(x)) + s * NC;
    atomicAdd(&g_cnt[c], 1u);
}

// ---------------- 3. scan stage 1: per-1024-tile ----------------
__global__ void __launch_bounds__(256) k_scan1() {
    __shared__ uint sm[256];
    int t = threadIdx.x;
    int base = blockIdx.x * 1024 + t * 4;
    uint c0 = g_cnt[base], c1 = g_cnt[base + 1], c2 = g_cnt[base + 2], c3 = g_cnt[base + 3];
    uint s = c0 + c1 + c2 + c3;
    sm[t] = s; __syncthreads();
    for (int off = 1; off < 256; off <<= 1) {
        uint v = (t >= off) ? sm[t - off] : 0u;
        __syncthreads();
        sm[t] += v;
        __syncthreads();
    }
    uint excl = sm[t] - s;
    g_scanpart[base]     = excl;
    g_scanpart[base + 1] = excl + c0;
    g_scanpart[base + 2] = excl + c0 + c1;
    g_scanpart[base + 3] = excl + c0 + c1 + c2;
    if (t == 255) g_bsum[blockIdx.x] = sm[255];
}

// ---------------- 4. scan stage 2: 512 tile sums ----------------
__global__ void __launch_bounds__(512) k_scan2() {
    __shared__ uint sm[512];
    int t = threadIdx.x;
    uint s = g_bsum[t];
    sm[t] = s; __syncthreads();
    for (int off = 1; off < 512; off <<= 1) {
        uint v = (t >= off) ? sm[t - off] : 0u;
        __syncthreads();
        sm[t] += v;
        __syncthreads();
    }
    g_boff[t] = sm[t] - s;   // exclusive
}

// ---------------- 5. scan stage 3: apply offsets ----------------
__global__ void __launch_bounds__(256) k_scan3() {
    int t = threadIdx.x;
    int base = blockIdx.x * 1024 + t * 4;
    uint off = g_boff[blockIdx.x];
#pragma unroll
    for (int k = 0; k < 4; k++) {
        uint v = g_scanpart[base + k] + off;
        g_start[base + k] = v;
        g_cursor[base + k] = v;
    }
    if (blockIdx.x == 511 && t == 255) g_start[NC2] = NALL;
}

// ---------------- 6. scatter (sorted by cell) ----------------
__global__ void __launch_bounds__(256) k_scatter(const float* __restrict__ pred,
                                                 const float* __restrict__ target) {
    int i = blockIdx.x * 256 + threadIdx.x;          // global original idx
    int s = i >> 15;
    int li = i & (NPTS - 1);
    const float* src = s ? target : pred;
    float x = src[3 * li], y = src[3 * li + 1], z = src[3 * li + 2];
    int c = ((cellof(z) * G + cellof(y)) * G + cellof(x)) + s * NC;
    uint pos = atomicAdd(&g_cursor[c], 1u);
    g_pts[pos] = make_float4(x, y, z, __int_as_float(i));
}

// ---------------- 7. query: expanding-ring exact NN ----------------
__device__ __forceinline__ void scan_range(uint k0, uint k1,
                                           float qx, float qy, float qz,
                                           float& best) {
#pragma unroll 2
    for (uint k = k0; k < k1; k++) {
        float4 p = g_pts[k];
        float dx = p.x - qx, dy = p.y - qy, dz = p.z - qz;
        best = fminf(best, fmaf(dx, dx, fmaf(dy, dy, dz * dz)));
    }
}

__global__ void __launch_bounds__(256) k_query() {
    int i = blockIdx.x * 256 + threadIdx.x;          // sorted position
    float4 q = g_pts[i];
    int s = i >> 15;                                 // set of this query
    int tb = (s ^ 1) * NC;                           // target grid base
    float qx = q.x, qy = q.y, qz = q.z;
    int cx = cellof(qx), cy = cellof(qy), cz = cellof(qz);

    // how far the query lies outside its (clamped) cell: keeps bound exact
    float ex = 0.0f;
    {
        float l = GLO + cx * GH; ex = fmaxf(ex, fmaxf(l - qx, qx - (l + GH)));
        l = GLO + cy * GH;       ex = fmaxf(ex, fmaxf(l - qy, qy - (l + GH)));
        l = GLO + cz * GH;       ex = fmaxf(ex, fmaxf(l - qz, qz - (l + GH)));
    }

    float best = FINF;
    for (int r = 0;; r++) {
        int z0 = max(cz - r, 0), z1 = min(cz + r, G - 1);
        int y0 = max(cy - r, 0), y1 = min(cy + r, G - 1);
        int x0 = max(cx - r, 0), x1 = min(cx + r, G - 1);
        for (int z = z0; z <= z1; z++) {
            bool zf = (z == cz - r) || (z == cz + r);
            int zb = (z * G) * G + tb;
            for (int y = y0; y <= y1; y++) {
                int cb = zb + y * G;
                if (zf || y == cy - r || y == cy + r) {
                    // full contiguous x-run as one CSR range
                    scan_range(g_start[cb + x0], g_start[cb + x1 + 1], qx, qy, qz, best);
                } else {
                    if (cx - r >= 0) {
                        int c = cb + cx - r;
                        scan_range(g_start[c], g_start[c + 1], qx, qy, qz, best);
                    }
                    if (cx + r < G) {
                        int c = cb + cx + r;
                        scan_range(g_start[c], g_start[c + 1], qx, qy, qz, best);
                    }
                }
            }
        }
        // all unexamined points differ by > r*GH - ex in some axis
        float bnd = (float)r * GH - ex;
        if (bnd > 0.0f && best <= bnd * bnd) break;
        if (r >= G) break;
    }
    g_minv[__float_as_int(q.w)] = best;   // write by ORIGINAL index: deterministic
}

// ---------------- 8-9. deterministic reduction ----------------
__global__ void __launch_bounds__(256) k_reduce1() {
    __shared__ float sm[256];
    int t = threadIdx.x;
    int base = blockIdx.x * 1024;
    float acc = 0.0f;
#pragma unroll
    for (int k = 0; k < 4; k++)
        acc += g_minv[base + t + k * 256];
    sm[t] = acc; __syncthreads();
    for (int stride = 128; stride > 0; stride >>= 1) {
        if (t < stride) sm[t] += sm[t + stride];
        __syncthreads();
    }
    if (t == 0) g_part[blockIdx.x] = sm[0];
}

__global__ void __launch_bounds__(64) k_reduce2(float* __restrict__ out) {
    __shared__ float sm[64];
    int t = threadIdx.x;
    sm[t] = g_part[t];
    __syncthreads();
    for (int stride = 32; stride > 0; stride >>= 1) {
        if (t < stride) sm[t] += sm[t + stride];
        __syncthreads();
    }
    if (t == 0) out[0] = sm[0] / (float)NPTS;
}

extern "C" void kernel_launch(void* const* d_in, const int* in_sizes, int n_in,
                              void* d_out, int out_size) {
    const float* pred   = (const float*)d_in[0];
    const float* target = (const float*)d_in[1];
    float* out = (float*)d_out;

    k_zero   <<<NC2 / 1024, 256>>>();
    k_hist   <<<NALL / 256, 256>>>(pred, target);
    k_scan1  <<<NC2 / 1024, 256>>>();
    k_scan2  <<<1, 512>>>();
    k_scan3  <<<NC2 / 1024, 256>>>();
    k_scatter<<<NALL / 256, 256>>>(pred, target);
    k_query  <<<NALL / 256, 256>>>();
    k_reduce1<<<RED1_BLOCKS, 256>>>();
    k_reduce2<<<1, 64>>>(out);
}

// round 7
// speedup vs baseline: 4.6836x; 4.6836x over previous
#include <cuda_runtime.h>
#include <cuda_bf16.h>

// ChamferLoss via exact uniform-grid nearest neighbor (G=32, box rescan).
// pred[32768,3], target[32768,3] float32, out = mean NN^2 both directions.
//
// 1. zero counts  2. histogram  3-5. hierarchical exclusive scan (CSR)
// 6. scatter (cell-sorted, carries original index)
// 7. query: expanding-BOX scan (full rescan per radius; 1 CSR range per row)
//    with exact termination bound r*h - ex
// 8-9. deterministic 2-stage sum.

#define NPTS   32768
#define NALL   65536
#define G      32
#define NC     (G*G*G)       // 32768 cells per set
#define NC2    (2*NC)        // 65536
#define GLO    (-4.0f)
#define GH     (0.25f)       // 8/32, exact
#define GINV   (4.0f)        // 1/GH, exact
#define FINF   3.4e38f
#define RED1_BLOCKS 64

__device__ uint    g_cnt[NC2];
__device__ uint    g_scanpart[NC2];
__device__ uint    g_bsum[64];
__device__ uint    g_boff[64];
__device__ uint    g_start[NC2 + 1];
__device__ uint    g_cursor[NC2];
__device__ float4  g_pts[NALL];      // cell-sorted; .w = original global idx bits
__device__ float   g_minv[NALL];     // per-ORIGINAL-index min sq distance
__device__ float   g_part[RED1_BLOCKS];

__device__ __forceinline__ int cellof(float v) {
    int c = (int)floorf((v - GLO) * GINV);
    return min(max(c, 0), G - 1);
}

// ---------------- 1. zero counts ----------------
__global__ void __launch_bounds__(256) k_zero() {
    int i = (blockIdx.x * 256 + threadIdx.x) * 4;
    *(uint4*)&g_cnt[i] = make_uint4(0, 0, 0, 0);
}

// ---------------- 2. histogram ----------------
__global__ void __launch_bounds__(256) k_hist(const float* __restrict__ pred,
                                              const float* __restrict__ target) {
    int i = blockIdx.x * 256 + threadIdx.x;          // 0..NALL-1
    int s = i >> 15;
    int li = i & (NPTS - 1);
    const float* src = s ? target : pred;
    float x = src[3 * li], y = src[3 * li + 1], z = src[3 * li + 2];
    int c = ((cellof(z) * G + cellof(y)) * G + cellof(x)) + s * NC;
    atomicAdd(&g_cnt[c], 1u);
}

// ---------------- 3. scan stage 1: per-1024-cell tile ----------------
__global__ void __launch_bounds__(256) k_scan1() {
    __shared__ uint sm[256];
    int t = threadIdx.x;
    int base = blockIdx.x * 1024 + t * 4;
    uint c0 = g_cnt[base], c1 = g_cnt[base + 1], c2 = g_cnt[base + 2], c3 = g_cnt[base + 3];
    uint s = c0 + c1 + c2 + c3;
    sm[t] = s; __syncthreads();
    for (int off = 1; off < 256; off <<= 1) {
        uint v = (t >= off) ? sm[t - off] : 0u;
        __syncthreads();
        sm[t] += v;
        __syncthreads();
    }
    uint excl = sm[t] - s;
    g_scanpart[base]     = excl;
    g_scanpart[base + 1] = excl + c0;
    g_scanpart[base + 2] = excl + c0 + c1;
    g_scanpart[base + 3] = excl + c0 + c1 + c2;
    if (t == 255) g_bsum[blockIdx.x] = sm[255];
}

// ---------------- 4. scan stage 2: 64 tile sums ----------------
__global__ void __launch_bounds__(64) k_scan2() {
    __shared__ uint sm[64];
    int t = threadIdx.x;
    uint s = g_bsum[t];
    sm[t] = s; __syncthreads();
    for (int off = 1; off < 64; off <<= 1) {
        uint v = (t >= off) ? sm[t - off] : 0u;
        __syncthreads();
        sm[t] += v;
        __syncthreads();
    }
    g_boff[t] = sm[t] - s;   // exclusive
}

// ---------------- 5. scan stage 3: apply offsets ----------------
__global__ void __launch_bounds__(256) k_scan3() {
    int t = threadIdx.x;
    int base = blockIdx.x * 1024 + t * 4;
    uint off = g_boff[blockIdx.x];
#pragma unroll
    for (int k = 0; k < 4; k++) {
        uint v = g_scanpart[base + k] + off;
        g_start[base + k] = v;
        g_cursor[base + k] = v;
    }
    if (blockIdx.x == 63 && t == 255) g_start[NC2] = NALL;
}

// ---------------- 6. scatter (sorted by cell) ----------------
__global__ void __launch_bounds__(256) k_scatter(const float* __restrict__ pred,
                                                 const float* __restrict__ target) {
    int i = blockIdx.x * 256 + threadIdx.x;          // global original idx
    int s = i >> 15;
    int li = i & (NPTS - 1);
    const float* src = s ? target : pred;
    float x = src[3 * li], y = src[3 * li + 1], z = src[3 * li + 2];
    int c = ((cellof(z) * G + cellof(y)) * G + cellof(x)) + s * NC;
    uint pos = atomicAdd(&g_cursor[c], 1u);
    g_pts[pos] = make_float4(x, y, z, __int_as_float(i));
}

// ---------------- 7. query: expanding-box exact NN ----------------
__device__ __forceinline__ void scan_range(uint k0, uint k1,
                                           float qx, float qy, float qz,
                                           float& best) {
    for (uint k = k0; k < k1; k++) {
        float4 p = g_pts[k];
        float dx = p.x - qx, dy = p.y - qy, dz = p.z - qz;
        best = fminf(best, fmaf(dx, dx, fmaf(dy, dy, dz * dz)));
    }
}

__global__ void __launch_bounds__(256) k_query() {
    int i = blockIdx.x * 256 + threadIdx.x;          // sorted position
    float4 q = g_pts[i];
    int s = i >> 15;                                 // set of this query
    int tb = (s ^ 1) * NC;                           // target grid base
    float qx = q.x, qy = q.y, qz = q.z;
    int cx = cellof(qx), cy = cellof(qy), cz = cellof(qz);

    // distance of the query outside its (clamped) cell: keeps bound exact
    float ex = 0.0f;
    {
        float l = GLO + cx * GH; ex = fmaxf(ex, fmaxf(l - qx, qx - (l + GH)));
        l = GLO + cy * GH;       ex = fmaxf(ex, fmaxf(l - qy, qy - (l + GH)));
        l = GLO + cz * GH;       ex = fmaxf(ex, fmaxf(l - qz, qz - (l + GH)));
    }

    float best = FINF;
    int r = 1;
    for (;;) {
        // scan the full (2r+1)^3 box, one CSR range per (z,y) row
        int z0 = max(cz - r, 0), z1 = min(cz + r, G - 1);
        int y0 = max(cy - r, 0), y1 = min(cy + r, G - 1);
        int x0 = max(cx - r, 0), x1 = min(cx + r, G - 1);
        for (int z = z0; z <= z1; z++) {
            for (int y = y0; y <= y1; y++) {
                int rb = (z * G + y) * G + tb;
                scan_range(g_start[rb + x0], g_start[rb + x1 + 1], qx, qy, qz, best);
            }
        }
        // unexamined cells differ by > r in some axis index
        float bnd = (float)r * GH - ex;
        if ((bnd > 0.0f && best <= bnd * bnd) || r >= G) break;
        r++;
    }
    g_minv[__float_as_int(q.w)] = best;   // write by ORIGINAL index: deterministic
}

// ---------------- 8-9. deterministic reduction ----------------
__global__ void __launch_bounds__(256) k_reduce1() {
    __shared__ float sm[256];
    int t = threadIdx.x;
    int base = blockIdx.x * 1024;
    float acc = 0.0f;
#pragma unroll
    for (int k = 0; k < 4; k++)
        acc += g_minv[base + t + k * 256];
    sm[t] = acc; __syncthreads();
    for (int stride = 128; stride > 0; stride >>= 1) {
        if (t < stride) sm[t] += sm[t + stride];
        __syncthreads();
    }
    if (t == 0) g_part[blockIdx.x] = sm[0];
}

__global__ void __launch_bounds__(64) k_reduce2(float* __restrict__ out) {
    __shared__ float sm[64];
    int t = threadIdx.x;
    sm[t] = g_part[t];
    __syncthreads();
    for (int stride = 32; stride > 0; stride >>= 1) {
        if (t < stride) sm[t] += sm[t + stride];
        __syncthreads();
    }
    if (t == 0) out[0] = sm[0] / (float)NPTS;
}

extern "C" void kernel_launch(void* const* d_in, const int* in_sizes, int n_in,
                              void* d_out, int out_size) {
    const float* pred   = (const float*)d_in[0];
    const float* target = (const float*)d_in[1];
    float* out = (float*)d_out;

    k_zero   <<<NC2 / 1024, 256>>>();
    k_hist   <<<NALL / 256, 256>>>(pred, target);
    k_scan1  <<<NC2 / 1024, 256>>>();
    k_scan2  <<<1, 64>>>();
    k_scan3  <<<NC2 / 1024, 256>>>();
    k_scatter<<<NALL / 256, 256>>>(pred, target);
    k_query  <<<NALL / 256, 256>>>();
    k_reduce1<<<RED1_BLOCKS, 256>>>();
    k_reduce2<<<1, 64>>>(out);
}

// round 8
// speedup vs baseline: 6.7187x; 1.4345x over previous
#include <cuda_runtime.h>
#include <cuda_bf16.h>

// ChamferLoss via exact uniform-grid nearest neighbor (G=32).
// pred[32768,3], target[32768,3] float32, out = mean NN^2 both directions.
//
// 1. zero counts  2. histogram  3. scan stage1 (per-tile)
// 4. scan stage2 (per-block prefix of tile sums folded in, writes CSR starts)
// 5. scatter (cell-sorted, carries original index)
// 6. query: center-row-first + slab-distance row pruning, exact termination
// 7. single-kernel deterministic reduction.

#define NPTS   32768
#define NALL   65536
#define G      32
#define NC     (G*G*G)       // 32768 cells per set
#define NC2    (2*NC)        // 65536
#define GLO    (-4.0f)
#define GH     (0.25f)       // 8/32, exact
#define GINV   (4.0f)        // 1/GH, exact
#define FINF   3.4e38f

__device__ uint    g_cnt[NC2];
__device__ uint    g_scanpart[NC2];
__device__ uint    g_bsum[64];
__device__ uint    g_start[NC2 + 1];
__device__ uint    g_cursor[NC2];
__device__ float4  g_pts[NALL];      // cell-sorted; .w = original global idx bits
__device__ float   g_minv[NALL];     // per-ORIGINAL-index min sq distance

__device__ __forceinline__ int cellof(float v) {
    int c = (int)floorf((v - GLO) * GINV);
    return min(max(c, 0), G - 1);
}
// distance from q to the slab of cell index c along one axis (0 if inside)
__device__ __forceinline__ float slabdist(float q, int c) {
    float l = GLO + c * GH;
    return fmaxf(0.0f, fmaxf(l - q, q - (l + GH)));
}

// ---------------- 1. zero counts ----------------
__global__ void __launch_bounds__(256) k_zero() {
    int i = (blockIdx.x * 256 + threadIdx.x) * 4;
    *(uint4*)&g_cnt[i] = make_uint4(0, 0, 0, 0);
}

// ---------------- 2. histogram ----------------
__global__ void __launch_bounds__(256) k_hist(const float* __restrict__ pred,
                                              const float* __restrict__ target) {
    int i = blockIdx.x * 256 + threadIdx.x;          // 0..NALL-1
    int s = i >> 15;
    int li = i & (NPTS - 1);
    const float* src = s ? target : pred;
    float x = src[3 * li], y = src[3 * li + 1], z = src[3 * li + 2];
    int c = ((cellof(z) * G + cellof(y)) * G + cellof(x)) + s * NC;
    atomicAdd(&g_cnt[c], 1u);
}

// ---------------- 3. scan stage 1: per-1024-cell tile ----------------
__global__ void __launch_bounds__(256) k_scan1() {
    __shared__ uint sm[256];
    int t = threadIdx.x;
    int base = blockIdx.x * 1024 + t * 4;
    uint c0 = g_cnt[base], c1 = g_cnt[base + 1], c2 = g_cnt[base + 2], c3 = g_cnt[base + 3];
    uint s = c0 + c1 + c2 + c3;
    sm[t] = s; __syncthreads();
    for (int off = 1; off < 256; off <<= 1) {
        uint v = (t >= off) ? sm[t - off] : 0u;
        __syncthreads();
        sm[t] += v;
        __syncthreads();
    }
    uint excl = sm[t] - s;
    g_scanpart[base]     = excl;
    g_scanpart[base + 1] = excl + c0;
    g_scanpart[base + 2] = excl + c0 + c1;
    g_scanpart[base + 3] = excl + c0 + c1 + c2;
    if (t == 255) g_bsum[blockIdx.x] = sm[255];
}

// ------ 4. scan stage 2: each block derives its own tile prefix, applies ----
__global__ void __launch_bounds__(256) k_scan2apply() {
    __shared__ uint soff;
    int t = threadIdx.x;
    if (t < 32) {
        // exclusive prefix of g_bsum over tiles < blockIdx.x (64 values, 2/lane)
        uint a = (2 * t     < (int)blockIdx.x) ? g_bsum[2 * t]     : 0u;
        uint b = (2 * t + 1 < (int)blockIdx.x) ? g_bsum[2 * t + 1] : 0u;
        uint v = a + b;
#pragma unroll
        for (int o = 16; o > 0; o >>= 1)
            v += __shfl_down_sync(0xFFFFFFFFu, v, o);
        if (t == 0) soff = v;
    }
    __syncthreads();
    uint off = soff;
    int base = blockIdx.x * 1024 + t * 4;
#pragma unroll
    for (int k = 0; k < 4; k++) {
        uint v = g_scanpart[base + k] + off;
        g_start[base + k] = v;
        g_cursor[base + k] = v;
    }
    if (blockIdx.x == 63 && t == 255) g_start[NC2] = NALL;
}

// ---------------- 5. scatter (sorted by cell) ----------------
__global__ void __launch_bounds__(256) k_scatter(const float* __restrict__ pred,
                                                 const float* __restrict__ target) {
    int i = blockIdx.x * 256 + threadIdx.x;          // global original idx
    int s = i >> 15;
    int li = i & (NPTS - 1);
    const float* src = s ? target : pred;
    float x = src[3 * li], y = src[3 * li + 1], z = src[3 * li + 2];
    int c = ((cellof(z) * G + cellof(y)) * G + cellof(x)) + s * NC;
    uint pos = atomicAdd(&g_cursor[c], 1u);
    g_pts[pos] = make_float4(x, y, z, __int_as_float(i));
}

// ---------------- 6. query: pruned expanding-box exact NN ----------------
__device__ __forceinline__ void scan_range(uint k0, uint k1,
                                           float qx, float qy, float qz,
                                           float& best) {
    for (uint k = k0; k < k1; k++) {
        float4 p = g_pts[k];
        float dx = p.x - qx, dy = p.y - qy, dz = p.z - qz;
        best = fminf(best, fmaf(dx, dx, fmaf(dy, dy, dz * dz)));
    }
}

__global__ void __launch_bounds__(256) k_query() {
    int i = blockIdx.x * 256 + threadIdx.x;          // sorted position
    float4 q = g_pts[i];
    int s = i >> 15;                                 // set of this query
    int tb = (s ^ 1) * NC;                           // target grid base
    float qx = q.x, qy = q.y, qz = q.z;
    int cx = cellof(qx), cy = cellof(qy), cz = cellof(qz);

    // distance of the query outside its (clamped) cell: keeps bound exact
    float ex = fmaxf(slabdist(qx, cx), fmaxf(slabdist(qy, cy), slabdist(qz, cz)));

    float best = FINF;

    // ---- r = 1: center row first (tight best), then pruned rows ----
    {
        int x0 = max(cx - 1, 0), x1 = min(cx + 1, G - 1);
        int rbc = (cz * G + cy) * G + tb;
        scan_range(g_start[rbc + x0], g_start[rbc + x1 + 1], qx, qy, qz, best);

        int z0 = max(cz - 1, 0), z1 = min(cz + 1, G - 1);
        int y0 = max(cy - 1, 0), y1 = min(cy + 1, G - 1);
        for (int z = z0; z <= z1; z++) {
            float dz = slabdist(qz, z);
            float dz2 = dz * dz;
            for (int y = y0; y <= y1; y++) {
                if (z == cz && y == cy) continue;
                float dy = slabdist(qy, y);
                if (fmaf(dy, dy, dz2) >= best) continue;   // row cannot improve
                int rb = (z * G + y) * G + tb;
                scan_range(g_start[rb + x0], g_start[rb + x1 + 1], qx, qy, qz, best);
            }
        }
    }

    // ---- escalation: full pruned box per radius, exact termination ----
    int r = 1;
    for (;;) {
        float bnd = (float)r * GH - ex;   // unexamined cells are farther than this
        if ((bnd > 0.0f && best <= bnd * bnd) || r >= G) break;
        r++;
        int z0 = max(cz - r, 0), z1 = min(cz + r, G - 1);
        int y0 = max(cy - r, 0), y1 = min(cy + r, G - 1);
        int x0 = max(cx - r, 0), x1 = min(cx + r, G - 1);
        for (int z = z0; z <= z1; z++) {
            float dz = slabdist(qz, z);
            float dz2 = dz * dz;
            for (int y = y0; y <= y1; y++) {
                float dy = slabdist(qy, y);
                if (fmaf(dy, dy, dz2) >= best) continue;
                int rb = (z * G + y) * G + tb;
                scan_range(g_start[rb + x0], g_start[rb + x1 + 1], qx, qy, qz, best);
            }
        }
    }
    g_minv[__float_as_int(q.w)] = best;   // write by ORIGINAL index: deterministic
}

// ---------------- 7. single-kernel deterministic reduction ----------------
__global__ void __launch_bounds__(1024) k_reduce(float* __restrict__ out) {
    __shared__ float sm[1024];
    int t = threadIdx.x;
    float acc = 0.0f;
#pragma unroll
    for (int k = 0; k < NALL / 1024; k++)
        acc += g_minv[t + k * 1024];
    sm[t] = acc; __syncthreads();
    for (int stride = 512; stride > 0; stride >>= 1) {
        if (t < stride) sm[t] += sm[t + stride];
        __syncthreads();
    }
    if (t == 0) out[0] = sm[0] / (float)NPTS;
}

extern "C" void kernel_launch(void* const* d_in, const int* in_sizes, int n_in,
                              void* d_out, int out_size) {
    const float* pred   = (const float*)d_in[0];
    const float* target = (const float*)d_in[1];
    float* out = (float*)d_out;

    k_zero      <<<NC2 / 1024, 256>>>();
    k_hist      <<<NALL / 256, 256>>>(pred, target);
    k_scan1     <<<NC2 / 1024, 256>>>();
    k_scan2apply<<<NC2 / 1024, 256>>>();
    k_scatter   <<<NALL / 256, 256>>>(pred, target);
    k_query     <<<NALL / 256, 256>>>();
    k_reduce    <<<1, 1024>>>(out);
}